// round 15
// baseline (speedup 1.0000x reference)
#include <cuda_runtime.h>
#include <cuda_fp16.h>
#include <math.h>

#define N_NODES 20000
#define N_PAD   20032                 // padded rows for 64-node mma tiles
#define E_EDGES 320000
#define ET      (E_EDGES + N_NODES)   // 340000
#define IN_DIM  256
#define HID     64
#define NH      4
#define C       64
#define HC      256
#define DFF     128
#define NL      4

typedef unsigned long long u64t;

// packed f32x2 helpers (FFMA2 path)
#define FMA2(d, a, b) asm("fma.rn.f32x2 %0, %1, %2, %0;" : "+l"(d) : "l"(a), "l"(b))
__device__ __forceinline__ u64t pk2(float lo, float hi) {
    u64t r; asm("mov.b64 %0, {%1, %2};" : "=l"(r) : "f"(lo), "f"(hi)); return r;
}
__device__ __forceinline__ float2 upk2(u64t v) {
    float2 f; asm("mov.b64 {%0, %1}, %2;" : "=f"(f.x), "=f"(f.y) : "l"(v)); return f;
}

// tensor-core helpers (validated R11-R13)
#define LDSM4(a0, a1, a2, a3, addr) \
    asm volatile("ldmatrix.sync.aligned.m8n8.x4.shared.b16 {%0,%1,%2,%3}, [%4];" \
                 : "=r"(a0), "=r"(a1), "=r"(a2), "=r"(a3) : "r"(addr))
#define MMA16816(cc, a0, a1, a2, a3, b0, b1) \
    asm volatile("mma.sync.aligned.m16n8k16.row.col.f32.f16.f16.f32 " \
                 "{%0,%1,%2,%3}, {%4,%5,%6,%7}, {%8,%9}, {%0,%1,%2,%3};" \
                 : "+f"((cc)[0]), "+f"((cc)[1]), "+f"((cc)[2]), "+f"((cc)[3]) \
                 : "r"(a0), "r"(a1), "r"(a2), "r"(a3), "r"(b0), "r"(b1))
__device__ __forceinline__ unsigned smem_u32(const void* p) {
    return (unsigned)__cvta_generic_to_shared(p);
}

// ---------------- static scratch (no cudaMalloc allowed) -----------------------
__device__ __half g_xh_h[N_NODES * HC];     // fp16 messages (L2-resident)
__device__ float  g_as [N_NODES * NH];
__device__ float  g_ad [N_NODES * NH];
__device__ __half g_out_h[N_PAD * HC];      // fp16 aggregated messages (pad rows = 0)
__device__ int    g_off[N_NODES + 1];
__device__ int    g_cur[N_NODES];
__device__ int    g_srcl[ET];               // CSR-by-dst: src node per slot
// fp16 col-major ("B") weights for mma: row j = contiguous K column
__device__ __align__(16) __half g_W1h[NL * DFF * HC];  // [l][j][k]
__device__ __align__(16) __half g_W2h[NL * HID * DFF]; // [l][j][k]
__device__ __align__(16) __half g_Wch[NL * HC * HID];  // [l][j][k]

#define SZ_W1 (NL * DFF * HC)   // 131072
#define SZ_W2 (NL * HID * DFF)  // 32768
#define SZ_WC (NL * HC * HID)   // 65536

// one-shot fp16 weight prep (launch #1; 229K threads)
__global__ void k_wprep(const float* __restrict__ W1, const float* __restrict__ W2,
                        const float* __restrict__ Wc) {
    int t = blockIdx.x * blockDim.x + threadIdx.x;
    if (t < SZ_W1) {
        int l = t / (DFF * HC), r = t % (DFF * HC);
        int j = r / HC, k = r % HC;
        g_W1h[t] = __float2half_rn(W1[(size_t)l * HC * DFF + k * DFF + j]);
    }
    int u = t - SZ_W1;
    if (u >= 0 && u < SZ_W2) {
        int l = u / (HID * DFF), r = u % (HID * DFF);
        int j = r / DFF, k = r % DFF;
        g_W2h[u] = __float2half_rn(W2[(size_t)l * DFF * HID + k * HID + j]);
    }
    int v = u - SZ_W2;
    if (v >= 0 && v < SZ_WC) {
        int l = v / (HC * HID), r = v % (HC * HID);
        int j = r / HID, k = r % HID;
        g_Wch[v] = __float2half_rn(Wc[(size_t)l * HID * HC + k * HC + j]);
    }
}

// ================= CSR construction (graph is layer-invariant) =================
__global__ void k_csr_init() {
    int i = blockIdx.x * blockDim.x + threadIdx.x;
    if (i < N_NODES) g_cur[i] = 1;       // self loop pre-counted
}

__global__ void k_csr_count(const int* __restrict__ ei) {
    int e = blockIdx.x * blockDim.x + threadIdx.x;
    if (e < E_EDGES) atomicAdd(&g_cur[ei[E_EDGES + e]], 1);
}

__global__ void k_csr_scan() {
    __shared__ int ps[1024];
    const int CH = 20;
    int t = threadIdx.x;
    int base = t * CH;
    int mysum = 0;
    for (int i = 0; i < CH; i++) { int idx = base + i; if (idx < N_NODES) mysum += g_cur[idx]; }
    ps[t] = mysum;
    __syncthreads();
    for (int d = 1; d < 1024; d <<= 1) {
        int v = (t >= d) ? ps[t - d] : 0;
        __syncthreads();
        ps[t] += v;
        __syncthreads();
    }
    int run = ps[t] - mysum;
    for (int i = 0; i < CH; i++) {
        int idx = base + i;
        if (idx < N_NODES) { int deg = g_cur[idx]; g_off[idx] = run; g_cur[idx] = run; run += deg; }
    }
    if (t == 1023) g_off[N_NODES] = ps[1023];
}

__global__ void k_csr_fill(const int* __restrict__ ei) {
    int e = blockIdx.x * blockDim.x + threadIdx.x;
    if (e >= ET) return;
    int src, dst;
    if (e < E_EDGES) { src = ei[e]; dst = ei[E_EDGES + e]; }
    else             { src = dst = e - E_EDGES; }
    int pos = atomicAdd(&g_cur[dst], 1);
    g_srcl[pos] = src;
}

// ====== embed (scalar FFMA2, R9 form) ==========================================
__global__ void __launch_bounds__(256, 4)
k_embed(const float* __restrict__ x, const float* __restrict__ We,
        const float* __restrict__ be, float* __restrict__ h) {
    int t = threadIdx.x;
    int jp = t & 31, g = t >> 5;               // g 0..7 -> nodes g*2, g*2+1
    int n0 = blockIdx.x * 16;
    __shared__ __align__(16) float4 xs[16 * 64];   // 16 KB
#pragma unroll
    for (int q = 0; q < 4; q++) {
        int fi = t + q * 256;
        int row = fi >> 6, c4 = fi & 63;
        xs[fi] = *(const float4*)(x + (size_t)(n0 + row) * IN_DIM + c4 * 4);
    }
    __syncthreads();
    u64t accA[2] = {0ULL, 0ULL}, accB[2] = {0ULL, 0ULL};
#pragma unroll 1
    for (int kc = 0; kc < 32; kc++) {          // K=256 in chunks of 8
        u64t wpA[4], wpB[4];
#pragma unroll
        for (int m = 0; m < 4; m++) {
            wpA[m] = pk2(We[(size_t)(kc * 8 + 2 * m) * HID + jp],
                         We[(size_t)(kc * 8 + 2 * m + 1) * HID + jp]);
            wpB[m] = pk2(We[(size_t)(kc * 8 + 2 * m) * HID + jp + 32],
                         We[(size_t)(kc * 8 + 2 * m + 1) * HID + jp + 32]);
        }
#pragma unroll
        for (int k4 = 0; k4 < 2; k4++) {
#pragma unroll
            for (int n = 0; n < 2; n++) {
                ulonglong2 v = ((const ulonglong2*)xs)[(g * 2 + n) * 64 + kc * 2 + k4];
                FMA2(accA[n], wpA[2 * k4],     v.x);
                FMA2(accA[n], wpA[2 * k4 + 1], v.y);
                FMA2(accB[n], wpB[2 * k4],     v.x);
                FMA2(accB[n], wpB[2 * k4 + 1], v.y);
            }
        }
    }
    float bA = be[jp], bB = be[jp + 32];
#pragma unroll
    for (int n = 0; n < 2; n++) {
        float2 fa = upk2(accA[n]), fb = upk2(accB[n]);
        h[(size_t)(n0 + g * 2 + n) * HID + jp]      = (fa.x + fa.y + bA) * 8.0f;
        h[(size_t)(n0 + g * 2 + n) * HID + jp + 32] = (fb.x + fb.y + bB) * 8.0f;
    }
}

// ====== xh = h @ Wc + attention, tensor cores, smem-staged weights (R13) =======
#define SXA 72    // A / W row stride (halves)
#define SXH 264   // xh staging stride (halves)
#define XPOOL (64 * SXA + 256 * SXA)
__global__ void __launch_bounds__(256, 2)
k_xh_att(const float* __restrict__ h, int l,
         const float* __restrict__ att_src, const float* __restrict__ att_dst) {
    int t = threadIdx.x, lane = t & 31, w = t >> 5;
    int n0 = blockIdx.x * 64;
    __shared__ __align__(16) __half pool[XPOOL];
    __shared__ float sAs[HC], sAd[HC];
    __half* At = pool;
    __half* Wt = pool + 64 * SXA;
    if (t < HC) { sAs[t] = att_src[t]; sAd[t] = att_dst[t]; }
    for (int i = t; i < 64 * 16; i += 256) {
        int row = i >> 4, c4 = i & 15;
        float4 v = make_float4(0.f, 0.f, 0.f, 0.f);
        if (n0 + row < N_NODES) v = *(const float4*)(h + (size_t)(n0 + row) * HID + c4 * 4);
        __half2* dst = (__half2*)(At + row * SXA + c4 * 4);
        dst[0] = __floats2half2_rn(v.x, v.y);
        dst[1] = __floats2half2_rn(v.z, v.w);
    }
    {
        const __half* Wch = g_Wch + (size_t)l * HC * HID;
        for (int i = t; i < 2048; i += 256) {
            int row = i >> 3, seg = i & 7;
            *(uint4*)(Wt + row * SXA + seg * 8) = *(const uint4*)(Wch + row * HID + seg * 8);
        }
    }
    __syncthreads();
    int g = lane >> 2, c = lane & 3;
    int m0 = (w & 3) * 16, ns = (w >> 2) * 128;
    unsigned abase = smem_u32(At);
    unsigned wbase = smem_u32(Wt);
    int rowA = m0 + (lane & 7) + ((lane >> 3) & 1) * 8;
    int colA = ((lane >> 4) & 1) * 8;
    int bq = lane >> 3, br = lane & 7;
    int bj_off = br + ((bq >> 1) << 3);
    int bk_off = (bq & 1) << 3;
    float acc[16][4];
#pragma unroll
    for (int nt = 0; nt < 16; nt++)
#pragma unroll
        for (int i = 0; i < 4; i++) acc[nt][i] = 0.f;
#pragma unroll
    for (int kt = 0; kt < 4; kt++) {
        unsigned a0, a1, a2, a3;
        LDSM4(a0, a1, a2, a3, abase + (unsigned)(rowA * SXA + kt * 16 + colA) * 2u);
#pragma unroll
        for (int nt = 0; nt < 16; nt += 2) {
            unsigned b0, b1, b2, b3;
            LDSM4(b0, b1, b2, b3,
                  wbase + (unsigned)((ns + nt * 8 + bj_off) * SXA + kt * 16 + bk_off) * 2u);
            MMA16816(acc[nt],     a0, a1, a2, a3, b0, b1);
            MMA16816(acc[nt + 1], a0, a1, a2, a3, b2, b3);
        }
    }
    __syncthreads();
#pragma unroll
    for (int nt = 0; nt < 16; nt++) {
        int col = ns + nt * 8 + 2 * c;
        *(__half2*)(pool + (m0 + g) * SXH + col)     = __floats2half2_rn(acc[nt][0], acc[nt][1]);
        *(__half2*)(pool + (m0 + 8 + g) * SXH + col) = __floats2half2_rn(acc[nt][2], acc[nt][3]);
    }
    __syncthreads();
    for (int i = t; i < 64 * 32; i += 256) {
        int row = i >> 5, c8 = i & 31;
        if (n0 + row < N_NODES)
            *(uint4*)(g_xh_h + (size_t)(n0 + row) * HC + c8 * 8) =
                *(const uint4*)(pool + row * SXH + c8 * 8);
    }
    {
        int node = t >> 2, hh = t & 3;
        const __half* rowp = pool + node * SXH + hh * 64;
        float s = 0.f, d = 0.f;
#pragma unroll
        for (int q = 0; q < 8; q++) {
            uint4 v = *(const uint4*)(rowp + q * 8);
            const __half2* hp = (const __half2*)&v;
#pragma unroll
            for (int u = 0; u < 4; u++) {
                float2 f = __half22float2(hp[u]);
                int col = hh * 64 + q * 8 + u * 2;
                s = fmaf(f.x, sAs[col], s); s = fmaf(f.y, sAs[col + 1], s);
                d = fmaf(f.x, sAd[col], d); d = fmaf(f.y, sAd[col + 1], d);
            }
        }
        if (n0 + node < N_NODES) {
            g_as[(size_t)(n0 + node) * NH + hh] = s;
            g_ad[(size_t)(n0 + node) * NH + hh] = d;
        }
    }
}

// GAT aggregation: one warp per dst node, online softmax, MLP=8 front-batched.
#define GAT_ACCUM(WG, V) do {                                                     \
    const __half2* hp = (const __half2*)&(V);                                     \
    float2 f0 = __half22float2(hp[0]), f1 = __half22float2(hp[1]);                \
    float2 f2 = __half22float2(hp[2]), f3 = __half22float2(hp[3]);                \
    a0 = fmaf(WG, f0.x, a0); a1 = fmaf(WG, f0.y, a1);                             \
    a2 = fmaf(WG, f1.x, a2); a3 = fmaf(WG, f1.y, a3);                             \
    a4 = fmaf(WG, f2.x, a4); a5 = fmaf(WG, f2.y, a5);                             \
    a6 = fmaf(WG, f3.x, a6); a7 = fmaf(WG, f3.y, a7);                             \
} while (0)

#define GAT_EDGE(Q, V) do {                                                       \
    float e = (Q) + ad; e = e > 0.f ? e : 0.2f * e;                               \
    if (e > m) {                                                                  \
        float corr = __expf(m - e);                                               \
        m = e; z *= corr;                                                         \
        a0 *= corr; a1 *= corr; a2 *= corr; a3 *= corr;                           \
        a4 *= corr; a5 *= corr; a6 *= corr; a7 *= corr;                           \
    }                                                                             \
    float wg = __expf(e - m);                                                     \
    z += wg;                                                                      \
    GAT_ACCUM(wg, V);                                                             \
} while (0)

__global__ void __launch_bounds__(256, 3)
k_gat(const float* __restrict__ bc) {
    int w = (blockIdx.x * blockDim.x + threadIdx.x) >> 5;
    if (w >= N_NODES) return;
    int lane = threadIdx.x & 31;
    int hh = lane >> 3;                  // head owning channels [lane*8, lane*8+8)
    int beg = g_off[w], end = g_off[w + 1];
    float ad = g_ad[w * NH + hh];
    float m = -INFINITY, z = 0.f;
    float a0 = 0, a1 = 0, a2 = 0, a3 = 0, a4 = 0, a5 = 0, a6 = 0, a7 = 0;
    int p = beg;
    for (; p + 8 <= end; p += 8) {       // MLP=8 front-batched, single rescale
        int s[8];
#pragma unroll
        for (int i = 0; i < 8; i++) s[i] = g_srcl[p + i];
        float q[8];
#pragma unroll
        for (int i = 0; i < 8; i++) q[i] = g_as[s[i] * NH + hh];
        uint4 v[8];
#pragma unroll
        for (int i = 0; i < 8; i++)
            v[i] = *(const uint4*)(g_xh_h + (size_t)s[i] * HC + lane * 8);
        float e[8];
#pragma unroll
        for (int i = 0; i < 8; i++) {
            float ev = q[i] + ad;
            e[i] = ev > 0.f ? ev : 0.2f * ev;
        }
        float eb = fmaxf(fmaxf(fmaxf(e[0], e[1]), fmaxf(e[2], e[3])),
                         fmaxf(fmaxf(e[4], e[5]), fmaxf(e[6], e[7])));
        if (eb > m) {
            float corr = __expf(m - eb);
            m = eb; z *= corr;
            a0 *= corr; a1 *= corr; a2 *= corr; a3 *= corr;
            a4 *= corr; a5 *= corr; a6 *= corr; a7 *= corr;
        }
#pragma unroll
        for (int i = 0; i < 8; i++) {
            float wg = __expf(e[i] - m);
            z += wg;
            GAT_ACCUM(wg, v[i]);
        }
    }
    for (; p + 4 <= end; p += 4) {       // MLP=4 tail batches
        int s0 = g_srcl[p], s1 = g_srcl[p + 1], s2 = g_srcl[p + 2], s3 = g_srcl[p + 3];
        float q0 = g_as[s0 * NH + hh];
        float q1 = g_as[s1 * NH + hh];
        float q2 = g_as[s2 * NH + hh];
        float q3 = g_as[s3 * NH + hh];
        uint4 v0 = *(const uint4*)(g_xh_h + (size_t)s0 * HC + lane * 8);
        uint4 v1 = *(const uint4*)(g_xh_h + (size_t)s1 * HC + lane * 8);
        uint4 v2 = *(const uint4*)(g_xh_h + (size_t)s2 * HC + lane * 8);
        uint4 v3 = *(const uint4*)(g_xh_h + (size_t)s3 * HC + lane * 8);
        float e0 = q0 + ad; e0 = e0 > 0.f ? e0 : 0.2f * e0;
        float e1 = q1 + ad; e1 = e1 > 0.f ? e1 : 0.2f * e1;
        float e2 = q2 + ad; e2 = e2 > 0.f ? e2 : 0.2f * e2;
        float e3 = q3 + ad; e3 = e3 > 0.f ? e3 : 0.2f * e3;
        float eb = fmaxf(fmaxf(e0, e1), fmaxf(e2, e3));
        if (eb > m) {
            float corr = __expf(m - eb);
            m = eb; z *= corr;
            a0 *= corr; a1 *= corr; a2 *= corr; a3 *= corr;
            a4 *= corr; a5 *= corr; a6 *= corr; a7 *= corr;
        }
        float w0 = __expf(e0 - m), w1 = __expf(e1 - m);
        float w2 = __expf(e2 - m), w3 = __expf(e3 - m);
        z += w0 + w1 + w2 + w3;
        GAT_ACCUM(w0, v0);
        GAT_ACCUM(w1, v1);
        GAT_ACCUM(w2, v2);
        GAT_ACCUM(w3, v3);
    }
    for (; p < end; p++) {
        int s0 = g_srcl[p];
        float q0 = g_as[s0 * NH + hh];
        uint4 v0 = *(const uint4*)(g_xh_h + (size_t)s0 * HC + lane * 8);
        GAT_EDGE(q0, v0);
    }
    float inv = 1.f / (z + 1e-16f);
    const float4* bcv = (const float4*)(bc + lane * 8);
    float4 c0 = bcv[0], c1 = bcv[1];
    __half2 q[4];
    q[0] = __floats2half2_rn(fmaf(a0, inv, c0.x), fmaf(a1, inv, c0.y));
    q[1] = __floats2half2_rn(fmaf(a2, inv, c0.z), fmaf(a3, inv, c0.w));
    q[2] = __floats2half2_rn(fmaf(a4, inv, c1.x), fmaf(a5, inv, c1.y));
    q[3] = __floats2half2_rn(fmaf(a6, inv, c1.z), fmaf(a7, inv, c1.w));
    *(uint4*)(g_out_h + (size_t)w * HC + lane * 8) = *(uint4*)q;
}

// ====== fused FFN via tensor cores (validated R11) =============================
#define SRA 264   // smem halves stride for X
#define SFB 136   // smem halves stride for ff
__global__ void __launch_bounds__(256, 2)
k_ffn(int l, const float* __restrict__ b1, const float* __restrict__ b2,
      const float* __restrict__ lng, const float* __restrict__ lnb,
      float* __restrict__ h) {
    int t = threadIdx.x, lane = t & 31, w = t >> 5;
    int n0 = blockIdx.x * 64;
    __shared__ __align__(16) __half pool_h[64 * SRA];  // 33 KB, staged
    __shared__ float2 stats[64];
    for (int i = t; i < 64 * 32; i += 256) {
        int row = i >> 5, c8 = i & 31;
        *(uint4*)(pool_h + row * SRA + c8 * 8) =
            *(const uint4*)(g_out_h + (size_t)(n0 + row) * HC + c8 * 8);
    }
    __syncthreads();
    int g = lane >> 2, c = lane & 3;
    int m0 = (w & 3) * 16;
    int nsA = (w >> 2) * 64;
    unsigned xbase = smem_u32(pool_h);
    int rowA = m0 + (lane & 7) + ((lane >> 3) & 1) * 8;
    int colA = ((lane >> 4) & 1) * 8;
    float acc[8][4];
#pragma unroll
    for (int nt = 0; nt < 8; nt++)
#pragma unroll
        for (int i = 0; i < 4; i++) acc[nt][i] = 0.f;
    const __half* W1h = g_W1h + (size_t)l * DFF * HC;
#pragma unroll 1
    for (int kt = 0; kt < 16; kt++) {
        unsigned a0, a1, a2, a3;
        LDSM4(a0, a1, a2, a3, xbase + (unsigned)(rowA * SRA + kt * 16 + colA) * 2u);
#pragma unroll
        for (int nt = 0; nt < 8; nt++) {
            const __half* bp = W1h + (size_t)(nsA + nt * 8 + g) * HC + kt * 16 + 2 * c;
            unsigned b0 = *(const unsigned*)bp;
            unsigned b1r = *(const unsigned*)(bp + 8);
            MMA16816(acc[nt], a0, a1, a2, a3, b0, b1r);
        }
    }
    __syncthreads();
    __half* ff = pool_h;
#pragma unroll
    for (int nt = 0; nt < 8; nt++) {
        int col = nsA + nt * 8 + 2 * c;
        float bA = b1[col], bB = b1[col + 1];
        float v0 = acc[nt][0] + bA, v1 = acc[nt][1] + bB;
        float v2 = acc[nt][2] + bA, v3 = acc[nt][3] + bB;
        float g0 = 0.5f * v0 * (1.0f + erff(v0 * 0.70710678118654752f));
        float g1 = 0.5f * v1 * (1.0f + erff(v1 * 0.70710678118654752f));
        float g2 = 0.5f * v2 * (1.0f + erff(v2 * 0.70710678118654752f));
        float g3 = 0.5f * v3 * (1.0f + erff(v3 * 0.70710678118654752f));
        *(__half2*)(ff + (m0 + g) * SFB + col)     = __floats2half2_rn(g0, g1);
        *(__half2*)(ff + (m0 + 8 + g) * SFB + col) = __floats2half2_rn(g2, g3);
    }
    __syncthreads();
    int nsB = (w >> 2) * 32;
    int rowB = m0 + (lane & 7) + ((lane >> 3) & 1) * 8;
    int colB = ((lane >> 4) & 1) * 8;
    float acc2[4][4];
#pragma unroll
    for (int nt = 0; nt < 4; nt++)
#pragma unroll
        for (int i = 0; i < 4; i++) acc2[nt][i] = 0.f;
    const __half* W2h = g_W2h + (size_t)l * HID * DFF;
#pragma unroll 1
    for (int kt = 0; kt < 8; kt++) {
        unsigned a0, a1, a2, a3;
        LDSM4(a0, a1, a2, a3, xbase + (unsigned)(rowB * SFB + kt * 16 + colB) * 2u);
#pragma unroll
        for (int nt = 0; nt < 4; nt++) {
            const __half* bp = W2h + (size_t)(nsB + nt * 8 + g) * DFF + kt * 16 + 2 * c;
            unsigned b0 = *(const unsigned*)bp;
            unsigned b1r = *(const unsigned*)(bp + 8);
            MMA16816(acc2[nt], a0, a1, a2, a3, b0, b1r);
        }
    }
    __syncthreads();
    float* sln = (float*)pool_h;         // 64 x 65 f32
#pragma unroll
    for (int nt = 0; nt < 4; nt++) {
        int col = nsB + nt * 8 + 2 * c;
        float bA = b2[col], bB = b2[col + 1];
        sln[(m0 + g) * 65 + col]         = acc2[nt][0] + bA;
        sln[(m0 + g) * 65 + col + 1]     = acc2[nt][1] + bB;
        sln[(m0 + 8 + g) * 65 + col]     = acc2[nt][2] + bA;
        sln[(m0 + 8 + g) * 65 + col + 1] = acc2[nt][3] + bB;
    }
    __syncthreads();
    int node = t >> 2, part = t & 3;
    float s = 0.f, sq = 0.f;
#pragma unroll
    for (int k = 0; k < 16; k++) {
        float v = sln[node * 65 + part * 16 + k];
        s += v; sq = fmaf(v, v, sq);
    }
    s  += __shfl_xor_sync(0xffffffffu, s, 1);  s  += __shfl_xor_sync(0xffffffffu, s, 2);
    sq += __shfl_xor_sync(0xffffffffu, sq, 1); sq += __shfl_xor_sync(0xffffffffu, sq, 2);
    if (part == 0) {
        float mean = s * (1.f / 64.f);
        stats[node] = make_float2(mean, sq * (1.f / 64.f) - mean * mean);
    }
    __syncthreads();
    if (n0 + node < N_NODES) {
        float2 st = stats[node];
        float rinv = rsqrtf(st.y + 1e-5f);
#pragma unroll
        for (int k = 0; k < 16; k++) {
            int col = part * 16 + k;
            float nv = (sln[node * 65 + col] - st.x) * rinv * lng[col] + lnb[col];
            h[(size_t)(n0 + node) * HID + col] += nv;
        }
    }
}

// ================= driver ======================================================
extern "C" void kernel_launch(void* const* d_in, const int* in_sizes, int n_in,
                              void* d_out, int out_size) {
    const float* x       = (const float*)d_in[0];
    const int*   ei      = (const int*)  d_in[1];
    const float* We      = (const float*)d_in[2];
    const float* be      = (const float*)d_in[3];
    const float* Wc      = (const float*)d_in[4];
    const float* att_src = (const float*)d_in[5];
    const float* att_dst = (const float*)d_in[6];
    const float* bc      = (const float*)d_in[7];
    const float* W1      = (const float*)d_in[8];
    const float* b1      = (const float*)d_in[9];
    const float* W2      = (const float*)d_in[10];
    const float* b2      = (const float*)d_in[11];
    const float* ln_g    = (const float*)d_in[12];
    const float* ln_b    = (const float*)d_in[13];

    float* h = (float*)d_out;

    // k_xh_att stays the profiled (4th) launch (control for this round).
    k_wprep    <<<896, 256>>>(W1, W2, Wc);                     // 1
    k_csr_init <<<(N_NODES + 255) / 256, 256>>>();             // 2
    k_embed    <<<1250, 256>>>(x, We, be, h);                  // 3
    k_xh_att   <<<313, 256>>>(h, 0, att_src, att_dst);         // 4 (layer 0)
    k_csr_count<<<(E_EDGES + 255) / 256, 256>>>(ei);           // 5
    k_csr_scan <<<1, 1024>>>();                                // 6
    k_csr_fill <<<(ET + 255) / 256, 256>>>(ei);                // 7
    k_gat      <<<2500, 256>>>(bc);                            // 8 (layer 0)
    k_ffn      <<<313, 256>>>(0, b1, b2, ln_g, ln_b, h);       // 9 (layer 0)

    for (int l = 1; l < NL; l++) {
        k_xh_att<<<313, 256>>>(h, l, att_src + l * NH * C, att_dst + l * NH * C);
        k_gat   <<<2500, 256>>>(bc + l * HC);
        k_ffn   <<<313, 256>>>(l, b1 + l * DFF, b2 + l * HID,
                               ln_g + l * HID, ln_b + l * HID, h);
    }
}

// round 17
// speedup vs baseline: 1.0341x; 1.0341x over previous
#include <cuda_runtime.h>
#include <cuda_fp16.h>
#include <math.h>

#define N_NODES 20000
#define N_PAD   20032                 // padded rows for 64-node mma tiles
#define E_EDGES 320000
#define ET      (E_EDGES + N_NODES)   // 340000
#define IN_DIM  256
#define HID     64
#define NH      4
#define C       64
#define HC      256
#define DFF     128
#define NL      4

// tensor-core helpers (validated R11-R13)
#define LDSM4(a0, a1, a2, a3, addr) \
    asm volatile("ldmatrix.sync.aligned.m8n8.x4.shared.b16 {%0,%1,%2,%3}, [%4];" \
                 : "=r"(a0), "=r"(a1), "=r"(a2), "=r"(a3) : "r"(addr))
#define MMA16816(cc, a0, a1, a2, a3, b0, b1) \
    asm volatile("mma.sync.aligned.m16n8k16.row.col.f32.f16.f16.f32 " \
                 "{%0,%1,%2,%3}, {%4,%5,%6,%7}, {%8,%9}, {%0,%1,%2,%3};" \
                 : "+f"((cc)[0]), "+f"((cc)[1]), "+f"((cc)[2]), "+f"((cc)[3]) \
                 : "r"(a0), "r"(a1), "r"(a2), "r"(a3), "r"(b0), "r"(b1))
__device__ __forceinline__ unsigned smem_u32(const void* p) {
    return (unsigned)__cvta_generic_to_shared(p);
}

// ---------------- static scratch (no cudaMalloc allowed) -----------------------
__device__ __half g_xh_h[N_NODES * HC];     // fp16 messages (L2-resident)
__device__ float  g_as [N_NODES * NH];
__device__ float  g_ad [N_NODES * NH];
__device__ __half g_out_h[N_PAD * HC];      // fp16 aggregated messages (pad rows = 0)
__device__ int    g_off[N_NODES + 1];
__device__ int    g_cur[N_NODES];
__device__ int    g_srcl[ET];               // CSR-by-dst: src node per slot
// fp16 col-major ("B") weights for mma: row j = contiguous K column
__device__ __align__(16) __half g_W1h[NL * DFF * HC];  // [l][j][k]
__device__ __align__(16) __half g_W2h[NL * HID * DFF]; // [l][j][k]
__device__ __align__(16) __half g_Wch[NL * HC * HID];  // [l][j][k]
__device__ __align__(16) __half g_Weh[HID * IN_DIM];   // [j][k]

#define SZ_W1 (NL * DFF * HC)   // 131072
#define SZ_W2 (NL * HID * DFF)  // 32768
#define SZ_WC (NL * HC * HID)   // 65536
#define SZ_WE (HID * IN_DIM)    // 16384

// one-shot fp16 weight prep + CSR degree init (launch #1; 246K threads)
__global__ void k_wprep(const float* __restrict__ W1, const float* __restrict__ W2,
                        const float* __restrict__ Wc, const float* __restrict__ We) {
    int t = blockIdx.x * blockDim.x + threadIdx.x;
    if (t < N_NODES) g_cur[t] = 1;       // self loop pre-counted (csr_init merged)
    if (t < SZ_W1) {
        int l = t / (DFF * HC), r = t % (DFF * HC);
        int j = r / HC, k = r % HC;
        g_W1h[t] = __float2half_rn(W1[(size_t)l * HC * DFF + k * DFF + j]);
    }
    int u = t - SZ_W1;
    if (u >= 0 && u < SZ_W2) {
        int l = u / (HID * DFF), r = u % (HID * DFF);
        int j = r / DFF, k = r % DFF;
        g_W2h[u] = __float2half_rn(W2[(size_t)l * DFF * HID + k * HID + j]);
    }
    int v = u - SZ_W2;
    if (v >= 0 && v < SZ_WC) {
        int l = v / (HC * HID), r = v % (HC * HID);
        int j = r / HID, k = r % HID;
        g_Wch[v] = __float2half_rn(Wc[(size_t)l * HID * HC + k * HC + j]);
    }
    int q = v - SZ_WC;
    if (q >= 0 && q < SZ_WE) {
        int j = q >> 8, k = q & 255;
        g_Weh[q] = __float2half_rn(We[(size_t)k * HID + j]);
    }
}

// ================= CSR construction (graph is layer-invariant) =================
__global__ void k_csr_count(const int* __restrict__ ei) {
    int e = blockIdx.x * blockDim.x + threadIdx.x;
    if (e < E_EDGES) atomicAdd(&g_cur[ei[E_EDGES + e]], 1);
}

__global__ void k_csr_scan() {
    __shared__ int ps[1024];
    const int CH = 20;
    int t = threadIdx.x;
    int base = t * CH;
    int mysum = 0;
    for (int i = 0; i < CH; i++) { int idx = base + i; if (idx < N_NODES) mysum += g_cur[idx]; }
    ps[t] = mysum;
    __syncthreads();
    for (int d = 1; d < 1024; d <<= 1) {
        int v = (t >= d) ? ps[t - d] : 0;
        __syncthreads();
        ps[t] += v;
        __syncthreads();
    }
    int run = ps[t] - mysum;
    for (int i = 0; i < CH; i++) {
        int idx = base + i;
        if (idx < N_NODES) { int deg = g_cur[idx]; g_off[idx] = run; g_cur[idx] = run; run += deg; }
    }
    if (t == 1023) g_off[N_NODES] = ps[1023];
}

__global__ void k_csr_fill(const int* __restrict__ ei) {
    int e = blockIdx.x * blockDim.x + threadIdx.x;
    if (e >= ET) return;
    int src, dst;
    if (e < E_EDGES) { src = ei[e]; dst = ei[E_EDGES + e]; }
    else             { src = dst = e - E_EDGES; }
    int pos = atomicAdd(&g_cur[dst], 1);
    g_srcl[pos] = src;
}

// ====== embed via tensor cores: h = (x @ We + be) * 8 ==========================
// 64 nodes/block, 8 warps: warp = m-tile (w&3)*16 x n-stripe (w>>2)*32 (4 nt of 8).
#define SEA 264   // x tile stride (halves)
__global__ void __launch_bounds__(256, 2)
k_embed(const float* __restrict__ x, const float* __restrict__ be, float* __restrict__ h) {
    int t = threadIdx.x, lane = t & 31, w = t >> 5;
    int n0 = blockIdx.x * 64;
    __shared__ __align__(16) __half pool[64 * SEA];   // 33 KB
    // x tile fp32 -> fp16 [64 x 256], OOB rows zero
    for (int i = t; i < 64 * 64; i += 256) {
        int row = i >> 6, c4 = i & 63;
        float4 v = make_float4(0.f, 0.f, 0.f, 0.f);
        if (n0 + row < N_NODES) v = *(const float4*)(x + (size_t)(n0 + row) * IN_DIM + c4 * 4);
        __half2* dst = (__half2*)(pool + row * SEA + c4 * 4);
        dst[0] = __floats2half2_rn(v.x, v.y);
        dst[1] = __floats2half2_rn(v.z, v.w);
    }
    __syncthreads();
    int g = lane >> 2, c = lane & 3;
    int m0 = (w & 3) * 16, ns = (w >> 2) * 32;   // FIXED: 2 stripes x 32 cols = 64
    unsigned abase = smem_u32(pool);
    int rowA = m0 + (lane & 7) + ((lane >> 3) & 1) * 8;
    int colA = ((lane >> 4) & 1) * 8;
    float acc[4][4];
#pragma unroll
    for (int nt = 0; nt < 4; nt++)
#pragma unroll
        for (int i = 0; i < 4; i++) acc[nt][i] = 0.f;
#pragma unroll 1
    for (int kt = 0; kt < 16; kt++) {            // K=256
        unsigned a0, a1, a2, a3;
        LDSM4(a0, a1, a2, a3, abase + (unsigned)(rowA * SEA + kt * 16 + colA) * 2u);
#pragma unroll
        for (int nt = 0; nt < 4; nt++) {
            const __half* bp = g_Weh + (size_t)(ns + nt * 8 + g) * IN_DIM + kt * 16 + 2 * c;
            unsigned b0  = *(const unsigned*)bp;
            unsigned b1r = *(const unsigned*)(bp + 8);
            MMA16816(acc[nt], a0, a1, a2, a3, b0, b1r);
        }
    }
#pragma unroll
    for (int nt = 0; nt < 4; nt++) {
        int col = ns + nt * 8 + 2 * c;
        float bA = be[col], bB = be[col + 1];
        int r0 = n0 + m0 + g, r1 = n0 + m0 + 8 + g;
        if (r0 < N_NODES) {
            h[(size_t)r0 * HID + col]     = (acc[nt][0] + bA) * 8.0f;
            h[(size_t)r0 * HID + col + 1] = (acc[nt][1] + bB) * 8.0f;
        }
        if (r1 < N_NODES) {
            h[(size_t)r1 * HID + col]     = (acc[nt][2] + bA) * 8.0f;
            h[(size_t)r1 * HID + col + 1] = (acc[nt][3] + bB) * 8.0f;
        }
    }
}

// ====== xh = h @ Wc + attention, tensor cores, smem-staged weights (R13) =======
#define SXA 72    // A / W row stride (halves)
#define SXH 264   // xh staging stride (halves)
#define XPOOL (64 * SXA + 256 * SXA)
__global__ void __launch_bounds__(256, 2)
k_xh_att(const float* __restrict__ h, int l,
         const float* __restrict__ att_src, const float* __restrict__ att_dst) {
    int t = threadIdx.x, lane = t & 31, w = t >> 5;
    int n0 = blockIdx.x * 64;
    __shared__ __align__(16) __half pool[XPOOL];
    __shared__ float sAs[HC], sAd[HC];
    __half* At = pool;
    __half* Wt = pool + 64 * SXA;
    if (t < HC) { sAs[t] = att_src[t]; sAd[t] = att_dst[t]; }
    for (int i = t; i < 64 * 16; i += 256) {
        int row = i >> 4, c4 = i & 15;
        float4 v = make_float4(0.f, 0.f, 0.f, 0.f);
        if (n0 + row < N_NODES) v = *(const float4*)(h + (size_t)(n0 + row) * HID + c4 * 4);
        __half2* dst = (__half2*)(At + row * SXA + c4 * 4);
        dst[0] = __floats2half2_rn(v.x, v.y);
        dst[1] = __floats2half2_rn(v.z, v.w);
    }
    {
        const __half* Wch = g_Wch + (size_t)l * HC * HID;
        for (int i = t; i < 2048; i += 256) {
            int row = i >> 3, seg = i & 7;
            *(uint4*)(Wt + row * SXA + seg * 8) = *(const uint4*)(Wch + row * HID + seg * 8);
        }
    }
    __syncthreads();
    int g = lane >> 2, c = lane & 3;
    int m0 = (w & 3) * 16, ns = (w >> 2) * 128;
    unsigned abase = smem_u32(At);
    unsigned wbase = smem_u32(Wt);
    int rowA = m0 + (lane & 7) + ((lane >> 3) & 1) * 8;
    int colA = ((lane >> 4) & 1) * 8;
    int bq = lane >> 3, br = lane & 7;
    int bj_off = br + ((bq >> 1) << 3);
    int bk_off = (bq & 1) << 3;
    float acc[16][4];
#pragma unroll
    for (int nt = 0; nt < 16; nt++)
#pragma unroll
        for (int i = 0; i < 4; i++) acc[nt][i] = 0.f;
#pragma unroll
    for (int kt = 0; kt < 4; kt++) {
        unsigned a0, a1, a2, a3;
        LDSM4(a0, a1, a2, a3, abase + (unsigned)(rowA * SXA + kt * 16 + colA) * 2u);
#pragma unroll
        for (int nt = 0; nt < 16; nt += 2) {
            unsigned b0, b1, b2, b3;
            LDSM4(b0, b1, b2, b3,
                  wbase + (unsigned)((ns + nt * 8 + bj_off) * SXA + kt * 16 + bk_off) * 2u);
            MMA16816(acc[nt],     a0, a1, a2, a3, b0, b1);
            MMA16816(acc[nt + 1], a0, a1, a2, a3, b2, b3);
        }
    }
    __syncthreads();
#pragma unroll
    for (int nt = 0; nt < 16; nt++) {
        int col = ns + nt * 8 + 2 * c;
        *(__half2*)(pool + (m0 + g) * SXH + col)     = __floats2half2_rn(acc[nt][0], acc[nt][1]);
        *(__half2*)(pool + (m0 + 8 + g) * SXH + col) = __floats2half2_rn(acc[nt][2], acc[nt][3]);
    }
    __syncthreads();
    for (int i = t; i < 64 * 32; i += 256) {
        int row = i >> 5, c8 = i & 31;
        if (n0 + row < N_NODES)
            *(uint4*)(g_xh_h + (size_t)(n0 + row) * HC + c8 * 8) =
                *(const uint4*)(pool + row * SXH + c8 * 8);
    }
    {
        int node = t >> 2, hh = t & 3;
        const __half* rowp = pool + node * SXH + hh * 64;
        float s = 0.f, d = 0.f;
#pragma unroll
        for (int q = 0; q < 8; q++) {
            uint4 v = *(const uint4*)(rowp + q * 8);
            const __half2* hp = (const __half2*)&v;
#pragma unroll
            for (int u = 0; u < 4; u++) {
                float2 f = __half22float2(hp[u]);
                int col = hh * 64 + q * 8 + u * 2;
                s = fmaf(f.x, sAs[col], s); s = fmaf(f.y, sAs[col + 1], s);
                d = fmaf(f.x, sAd[col], d); d = fmaf(f.y, sAd[col + 1], d);
            }
        }
        if (n0 + node < N_NODES) {
            g_as[(size_t)(n0 + node) * NH + hh] = s;
            g_ad[(size_t)(n0 + node) * NH + hh] = d;
        }
    }
}

// GAT aggregation (R13 best form): warp per dst node, online softmax, 4-batch.
#define GAT_ACCUM(WG, V) do {                                                     \
    const __half2* hp = (const __half2*)&(V);                                     \
    float2 f0 = __half22float2(hp[0]), f1 = __half22float2(hp[1]);                \
    float2 f2 = __half22float2(hp[2]), f3 = __half22float2(hp[3]);                \
    a0 = fmaf(WG, f0.x, a0); a1 = fmaf(WG, f0.y, a1);                             \
    a2 = fmaf(WG, f1.x, a2); a3 = fmaf(WG, f1.y, a3);                             \
    a4 = fmaf(WG, f2.x, a4); a5 = fmaf(WG, f2.y, a5);                             \
    a6 = fmaf(WG, f3.x, a6); a7 = fmaf(WG, f3.y, a7);                             \
} while (0)

#define GAT_EDGE(Q, V) do {                                                       \
    float e = (Q) + ad; e = e > 0.f ? e : 0.2f * e;                               \
    if (e > m) {                                                                  \
        float corr = __expf(m - e);                                               \
        m = e; z *= corr;                                                         \
        a0 *= corr; a1 *= corr; a2 *= corr; a3 *= corr;                           \
        a4 *= corr; a5 *= corr; a6 *= corr; a7 *= corr;                           \
    }                                                                             \
    float wg = __expf(e - m);                                                     \
    z += wg;                                                                      \
    GAT_ACCUM(wg, V);                                                             \
} while (0)

__global__ void k_gat(const float* __restrict__ bc) {
    int w = (blockIdx.x * blockDim.x + threadIdx.x) >> 5;
    if (w >= N_NODES) return;
    int lane = threadIdx.x & 31;
    int hh = lane >> 3;                  // head owning channels [lane*8, lane*8+8)
    int beg = g_off[w], end = g_off[w + 1];
    float ad = g_ad[w * NH + hh];
    float m = -INFINITY, z = 0.f;
    float a0 = 0, a1 = 0, a2 = 0, a3 = 0, a4 = 0, a5 = 0, a6 = 0, a7 = 0;
    int p = beg;
    for (; p + 4 <= end; p += 4) {       // MLP=4 front-batched, single rescale
        int s0 = g_srcl[p], s1 = g_srcl[p + 1], s2 = g_srcl[p + 2], s3 = g_srcl[p + 3];
        float q0 = g_as[s0 * NH + hh];
        float q1 = g_as[s1 * NH + hh];
        float q2 = g_as[s2 * NH + hh];
        float q3 = g_as[s3 * NH + hh];
        uint4 v0 = *(const uint4*)(g_xh_h + (size_t)s0 * HC + lane * 8);
        uint4 v1 = *(const uint4*)(g_xh_h + (size_t)s1 * HC + lane * 8);
        uint4 v2 = *(const uint4*)(g_xh_h + (size_t)s2 * HC + lane * 8);
        uint4 v3 = *(const uint4*)(g_xh_h + (size_t)s3 * HC + lane * 8);
        float e0 = q0 + ad; e0 = e0 > 0.f ? e0 : 0.2f * e0;
        float e1 = q1 + ad; e1 = e1 > 0.f ? e1 : 0.2f * e1;
        float e2 = q2 + ad; e2 = e2 > 0.f ? e2 : 0.2f * e2;
        float e3 = q3 + ad; e3 = e3 > 0.f ? e3 : 0.2f * e3;
        float eb = fmaxf(fmaxf(e0, e1), fmaxf(e2, e3));
        if (eb > m) {
            float corr = __expf(m - eb);
            m = eb; z *= corr;
            a0 *= corr; a1 *= corr; a2 *= corr; a3 *= corr;
            a4 *= corr; a5 *= corr; a6 *= corr; a7 *= corr;
        }
        float w0 = __expf(e0 - m), w1 = __expf(e1 - m);
        float w2 = __expf(e2 - m), w3 = __expf(e3 - m);
        z += w0 + w1 + w2 + w3;
        GAT_ACCUM(w0, v0);
        GAT_ACCUM(w1, v1);
        GAT_ACCUM(w2, v2);
        GAT_ACCUM(w3, v3);
    }
    for (; p < end; p++) {
        int s0 = g_srcl[p];
        float q0 = g_as[s0 * NH + hh];
        uint4 v0 = *(const uint4*)(g_xh_h + (size_t)s0 * HC + lane * 8);
        GAT_EDGE(q0, v0);
    }
    float inv = 1.f / (z + 1e-16f);
    const float4* bcv = (const float4*)(bc + lane * 8);
    float4 c0 = bcv[0], c1 = bcv[1];
    __half2 q[4];
    q[0] = __floats2half2_rn(fmaf(a0, inv, c0.x), fmaf(a1, inv, c0.y));
    q[1] = __floats2half2_rn(fmaf(a2, inv, c0.z), fmaf(a3, inv, c0.w));
    q[2] = __floats2half2_rn(fmaf(a4, inv, c1.x), fmaf(a5, inv, c1.y));
    q[3] = __floats2half2_rn(fmaf(a6, inv, c1.z), fmaf(a7, inv, c1.w));
    *(uint4*)(g_out_h + (size_t)w * HC + lane * 8) = *(uint4*)q;
}

// ====== fused FFN via tensor cores (validated R11) =============================
#define SRA 264   // smem halves stride for X
#define SFB 136   // smem halves stride for ff
__global__ void __launch_bounds__(256, 2)
k_ffn(int l, const float* __restrict__ b1, const float* __restrict__ b2,
      const float* __restrict__ lng, const float* __restrict__ lnb,
      float* __restrict__ h) {
    int t = threadIdx.x, lane = t & 31, w = t >> 5;
    int n0 = blockIdx.x * 64;
    __shared__ __align__(16) __half pool_h[64 * SRA];  // 33 KB, staged
    __shared__ float2 stats[64];
    for (int i = t; i < 64 * 32; i += 256) {
        int row = i >> 5, c8 = i & 31;
        *(uint4*)(pool_h + row * SRA + c8 * 8) =
            *(const uint4*)(g_out_h + (size_t)(n0 + row) * HC + c8 * 8);
    }
    __syncthreads();
    int g = lane >> 2, c = lane & 3;
    int m0 = (w & 3) * 16;
    int nsA = (w >> 2) * 64;
    unsigned xbase = smem_u32(pool_h);
    int rowA = m0 + (lane & 7) + ((lane >> 3) & 1) * 8;
    int colA = ((lane >> 4) & 1) * 8;
    float acc[8][4];
#pragma unroll
    for (int nt = 0; nt < 8; nt++)
#pragma unroll
        for (int i = 0; i < 4; i++) acc[nt][i] = 0.f;
    const __half* W1h = g_W1h + (size_t)l * DFF * HC;
#pragma unroll 1
    for (int kt = 0; kt < 16; kt++) {
        unsigned a0, a1, a2, a3;
        LDSM4(a0, a1, a2, a3, xbase + (unsigned)(rowA * SRA + kt * 16 + colA) * 2u);
#pragma unroll
        for (int nt = 0; nt < 8; nt++) {
            const __half* bp = W1h + (size_t)(nsA + nt * 8 + g) * HC + kt * 16 + 2 * c;
            unsigned b0 = *(const unsigned*)bp;
            unsigned b1r = *(const unsigned*)(bp + 8);
            MMA16816(acc[nt], a0, a1, a2, a3, b0, b1r);
        }
    }
    __syncthreads();
    __half* ff = pool_h;
#pragma unroll
    for (int nt = 0; nt < 8; nt++) {
        int col = nsA + nt * 8 + 2 * c;
        float bA = b1[col], bB = b1[col + 1];
        float v0 = acc[nt][0] + bA, v1 = acc[nt][1] + bB;
        float v2 = acc[nt][2] + bA, v3 = acc[nt][3] + bB;
        float g0 = 0.5f * v0 * (1.0f + erff(v0 * 0.70710678118654752f));
        float g1 = 0.5f * v1 * (1.0f + erff(v1 * 0.70710678118654752f));
        float g2 = 0.5f * v2 * (1.0f + erff(v2 * 0.70710678118654752f));
        float g3 = 0.5f * v3 * (1.0f + erff(v3 * 0.70710678118654752f));
        *(__half2*)(ff + (m0 + g) * SFB + col)     = __floats2half2_rn(g0, g1);
        *(__half2*)(ff + (m0 + 8 + g) * SFB + col) = __floats2half2_rn(g2, g3);
    }
    __syncthreads();
    int nsB = (w >> 2) * 32;
    int rowB = m0 + (lane & 7) + ((lane >> 3) & 1) * 8;
    int colB = ((lane >> 4) & 1) * 8;
    float acc2[4][4];
#pragma unroll
    for (int nt = 0; nt < 4; nt++)
#pragma unroll
        for (int i = 0; i < 4; i++) acc2[nt][i] = 0.f;
    const __half* W2h = g_W2h + (size_t)l * HID * DFF;
#pragma unroll 1
    for (int kt = 0; kt < 8; kt++) {
        unsigned a0, a1, a2, a3;
        LDSM4(a0, a1, a2, a3, xbase + (unsigned)(rowB * SFB + kt * 16 + colB) * 2u);
#pragma unroll
        for (int nt = 0; nt < 4; nt++) {
            const __half* bp = W2h + (size_t)(nsB + nt * 8 + g) * DFF + kt * 16 + 2 * c;
            unsigned b0 = *(const unsigned*)bp;
            unsigned b1r = *(const unsigned*)(bp + 8);
            MMA16816(acc2[nt], a0, a1, a2, a3, b0, b1r);
        }
    }
    __syncthreads();
    float* sln = (float*)pool_h;         // 64 x 65 f32
#pragma unroll
    for (int nt = 0; nt < 4; nt++) {
        int col = nsB + nt * 8 + 2 * c;
        float bA = b2[col], bB = b2[col + 1];
        sln[(m0 + g) * 65 + col]         = acc2[nt][0] + bA;
        sln[(m0 + g) * 65 + col + 1]     = acc2[nt][1] + bB;
        sln[(m0 + 8 + g) * 65 + col]     = acc2[nt][2] + bA;
        sln[(m0 + 8 + g) * 65 + col + 1] = acc2[nt][3] + bB;
    }
    __syncthreads();
    int node = t >> 2, part = t & 3;
    float s = 0.f, sq = 0.f;
#pragma unroll
    for (int k = 0; k < 16; k++) {
        float v = sln[node * 65 + part * 16 + k];
        s += v; sq = fmaf(v, v, sq);
    }
    s  += __shfl_xor_sync(0xffffffffu, s, 1);  s  += __shfl_xor_sync(0xffffffffu, s, 2);
    sq += __shfl_xor_sync(0xffffffffu, sq, 1); sq += __shfl_xor_sync(0xffffffffu, sq, 2);
    if (part == 0) {
        float mean = s * (1.f / 64.f);
        stats[node] = make_float2(mean, sq * (1.f / 64.f) - mean * mean);
    }
    __syncthreads();
    if (n0 + node < N_NODES) {
        float2 st = stats[node];
        float rinv = rsqrtf(st.y + 1e-5f);
#pragma unroll
        for (int k = 0; k < 16; k++) {
            int col = part * 16 + k;
            float nv = (sln[node * 65 + col] - st.x) * rinv * lng[col] + lnb[col];
            h[(size_t)(n0 + node) * HID + col] += nv;
        }
    }
}

// ================= driver ======================================================
extern "C" void kernel_launch(void* const* d_in, const int* in_sizes, int n_in,
                              void* d_out, int out_size) {
    const float* x       = (const float*)d_in[0];
    const int*   ei      = (const int*)  d_in[1];
    const float* We      = (const float*)d_in[2];
    const float* be      = (const float*)d_in[3];
    const float* Wc      = (const float*)d_in[4];
    const float* att_src = (const float*)d_in[5];
    const float* att_dst = (const float*)d_in[6];
    const float* bc      = (const float*)d_in[7];
    const float* W1      = (const float*)d_in[8];
    const float* b1      = (const float*)d_in[9];
    const float* W2      = (const float*)d_in[10];
    const float* b2      = (const float*)d_in[11];
    const float* ln_g    = (const float*)d_in[12];
    const float* ln_b    = (const float*)d_in[13];

    float* h = (float*)d_out;

    // k_embed (fixed HMMA kernel) is the profiled (4th) launch this round.
    k_wprep    <<<960, 256>>>(W1, W2, Wc, We);                 // 1 (incl. csr_init)
    k_csr_count<<<(E_EDGES + 255) / 256, 256>>>(ei);           // 2
    k_csr_scan <<<1, 1024>>>();                                // 3
    k_embed    <<<313, 256>>>(x, be, h);                       // 4 (profiled)
    k_csr_fill <<<(ET + 255) / 256, 256>>>(ei);                // 5
    k_xh_att   <<<313, 256>>>(h, 0, att_src, att_dst);         // 6 (layer 0)
    k_gat      <<<2500, 256>>>(bc);                            // 7 (layer 0)
    k_ffn      <<<313, 256>>>(0, b1, b2, ln_g, ln_b, h);       // 8 (layer 0)

    for (int l = 1; l < NL; l++) {
        k_xh_att<<<313, 256>>>(h, l, att_src + l * NH * C, att_dst + l * NH * C);
        k_gat   <<<2500, 256>>>(bc + l * HC);
        k_ffn   <<<313, 256>>>(l, b1 + l * DFF, b2 + l * HID,
                               ln_g + l * HID, ln_b + l * HID, h);
    }
}